// round 17
// baseline (speedup 1.0000x reference)
#include <cuda_runtime.h>
#include <cuda_bf16.h>
#include <cuda_fp16.h>
#include <math.h>
#include <stdint.h>

// ---------------- problem constants ----------------------------------------
#define B_ 1024
#define T_ 64
#define D_ 512
#define HD_ 512
#define L_ 3
#define NG 2048          // 4*HD gate columns (gate-interleaved)
#define KK 1024          // D + HD fused K
#define FN_ 64
#define ATT 63
#define NCELL (T_ * L_)          // 192
#define NITEM (NCELL * 64)       // 12288 items (128x256 tiles)

// tile geometry (global layout == smem stage image)
#define KCH 64
#define NCH (KK / KCH)            // 16 chunks
#define ROWB 144                  // 128B payload + 16B pad (conflict-free ldmatrix)
#define TB 18432                  // A tile: 128 rows (128*ROWB)
#define TBB 36864                 // B tile: 256 rows (256*ROWB)
#define A_OFF 0
#define B_OFF (TB)
#define STAGE_BYTES (TB + TBB)    // 55296
#define NSTAGE 4
#define PREF 3
#define DYN_SMEM (NSTAGE * STAGE_BYTES)  // 221184 (1 CTA/SM)
#define NTHR 256
#define NPERS 148

// ---------------- device scratch (tiled operand storage, all fp16) ----------
__device__ __align__(128) uint8_t g_Wt[(size_t)L_ * 8 * 16 * TBB];
__device__ __align__(128) uint8_t g_xt[(size_t)T_ * 64 * TB];
__device__ __align__(128) uint8_t g_Ht[(size_t)(T_ + 1) * L_ * 64 * TB];
__device__ float g_c[(size_t)L_ * B_ * HD_];
__device__ __align__(16) float g_bias[L_ * NG];
__device__ __align__(16) float g_ys[(size_t)T_ * B_ * HD_];
__device__ float g_effw[577];
__device__ int g_next;
__device__ int g_cnt[T_ * L_ * 8];     // [t][l][mBi] -> arrives 0..8
__device__ int g_cell_tl[NCELL];       // diagonal-major (t<<2)|l

// ---------------- small asm helpers ----------------------------------------
__device__ __forceinline__ uint32_t smem_u32(const void* p) {
    uint32_t a;
    asm("{ .reg .u64 t; cvta.to.shared.u64 t, %1; cvt.u32.u64 %0, t; }" : "=r"(a) : "l"(p));
    return a;
}
__device__ __forceinline__ void cp_bulk(uint32_t dst, const void* src, uint32_t bytes, uint32_t mbar) {
    asm volatile("cp.async.bulk.shared::cluster.global.mbarrier::complete_tx::bytes [%0], [%1], %2, [%3];"
                 :: "r"(dst), "l"(src), "r"(bytes), "r"(mbar) : "memory");
}
#define MBARRIER_INIT(addr, cnt) \
    asm volatile("mbarrier.init.shared.b64 [%0], %1;" :: "r"((uint32_t)(addr)), "r"((uint32_t)(cnt)) : "memory")
#define MBARRIER_ARRIVE(addr) \
    asm volatile("mbarrier.arrive.shared.b64 _, [%0];" :: "r"((uint32_t)(addr)) : "memory")
#define MBARRIER_EXPECT_TX(addr, tx) \
    asm volatile("mbarrier.arrive.expect_tx.shared.b64 _, [%0], %1;" :: "r"((uint32_t)(addr)), "r"((uint32_t)(tx)) : "memory")
#define MBARRIER_WAIT_PARITY(addr, par) do { \
    uint32_t _m = (uint32_t)(addr); uint32_t _p = (uint32_t)(par); uint32_t _d; \
    asm volatile("{ .reg .pred p; mbarrier.try_wait.parity.acquire.cta.shared::cta.b64 p, [%1], %2; selp.b32 %0,1,0,p; }" \
        : "=r"(_d) : "r"(_m), "r"(_p) : "memory"); \
    if (!_d) { \
        asm volatile("{ .reg .pred P1; WL%=: mbarrier.try_wait.parity.acquire.cta.shared::cta.b64 P1, [%0], %1, 0x989680; @P1 bra.uni WD%=; bra.uni WL%=; WD%=: }" \
            :: "r"(_m), "r"(_p) : "memory"); \
    } } while (0)

__device__ __forceinline__ int ld_acq(const int* p) {
    int v;
    asm volatile("ld.acquire.gpu.global.s32 %0, [%1];" : "=r"(v) : "l"(p) : "memory");
    return v;
}
__device__ __forceinline__ void red_rel_add1(int* p) {
    asm volatile("red.release.gpu.global.add.s32 [%0], %1;" :: "l"(p), "r"(1) : "memory");
}

__device__ __forceinline__ void ldsm4(uint32_t* r, uint32_t addr) {
    asm volatile("ldmatrix.sync.aligned.m8n8.x4.shared.b16 {%0,%1,%2,%3}, [%4];"
                 : "=r"(r[0]), "=r"(r[1]), "=r"(r[2]), "=r"(r[3]) : "r"(addr));
}
__device__ __forceinline__ void mma_f16(float* c, const uint32_t* a, const uint32_t* b) {
    asm volatile("mma.sync.aligned.m16n8k16.row.col.f32.f16.f16.f32 "
                 "{%0,%1,%2,%3}, {%4,%5,%6,%7}, {%8,%9}, {%0,%1,%2,%3};"
                 : "+f"(c[0]), "+f"(c[1]), "+f"(c[2]), "+f"(c[3])
                 : "r"(a[0]), "r"(a[1]), "r"(a[2]), "r"(a[3]), "r"(b[0]), "r"(b[1]));
}
__device__ __forceinline__ float sigf(float x) { return 1.f / (1.f + expf(-x)); }

// ---------------- prep kernels ---------------------------------------------
__global__ void prep_w_kernel(const float* __restrict__ W_ih, const float* __restrict__ W_hh,
                              const float* __restrict__ b_ih, const float* __restrict__ b_hh) {
    size_t idx = (size_t)blockIdx.x * blockDim.x + threadIdx.x;
    const size_t total = (size_t)L_ * NG * KK;
    if (idx < total) {
        int l = (int)(idx / ((size_t)NG * KK));
        size_t r = idx % ((size_t)NG * KK);
        int n = (int)(r / KK), k = (int)(r % KK);
        int oc = (n & 3) * HD_ + (n >> 2);
        float v = (k < D_) ? W_ih[((size_t)l * NG + oc) * D_ + k]
                           : W_hh[((size_t)l * NG + oc) * HD_ + (k - D_)];
        size_t blk = ((size_t)l * 8 + (n >> 8)) * 16 + (k >> 6);
        uint8_t* p = g_Wt + blk * TBB + (uint32_t)(n & 255) * ROWB + (uint32_t)(k & 63) * 2;
        *(__half*)p = __float2half(v);
    }
    if (idx < (size_t)L_ * NG) {
        int l = (int)(idx / NG), n = (int)(idx % NG);
        int oc = (n & 3) * HD_ + (n >> 2);
        g_bias[idx] = b_ih[(size_t)l * NG + oc] + b_hh[(size_t)l * NG + oc];
    }
}

__global__ void prep_misc_kernel(const float* __restrict__ x,
                                 const float* __restrict__ lin2_W, const float* __restrict__ lin2_b,
                                 const float* __restrict__ out_W, const float* __restrict__ out_b) {
    size_t idx = (size_t)blockIdx.x * blockDim.x + threadIdx.x;
    const size_t totx = (size_t)T_ * B_ * D_;
    if (idx < totx) {
        int t = (int)(idx / ((size_t)B_ * D_));
        size_t r = idx % ((size_t)B_ * D_);
        int b = (int)(r / D_), d = (int)(r % D_);
        float v = x[((size_t)b * T_ + t) * D_ + d];
        size_t blk = (size_t)t * 64 + (size_t)(b >> 7) * 8 + (d >> 6);
        uint8_t* p = g_xt + blk * TB + (uint32_t)(b & 127) * ROWB + (uint32_t)(d & 63) * 2;
        *(__half*)p = __float2half(v);
    }
    const size_t hz = (size_t)L_ * 64 * TB / 4;
    if (idx < hz) ((uint32_t*)g_Ht)[idx] = 0;
    if (idx < (size_t)L_ * B_ * HD_) g_c[idx] = 0.f;
    if (idx < (size_t)(T_ * L_ * 8)) g_cnt[idx] = 0;
    if (idx == 0) {
        g_next = 0;
        int i = 0;
        for (int d = 0; d < T_ + L_ - 1; d++) {
            int lmin = d - (T_ - 1); if (lmin < 0) lmin = 0;
            int lmax = (d < L_ - 1) ? d : (L_ - 1);
            for (int l = lmin; l <= lmax; l++) g_cell_tl[i++] = ((d - l) << 2) | l;
        }
    }
    if (idx < 576) {
        float a = 0.f;
        for (int j = 0; j < HD_; j++) a += out_W[j] * lin2_W[(size_t)j * 576 + idx];
        g_effw[idx] = a;
    } else if (idx == 576) {
        float a = out_b[0];
        for (int j = 0; j < HD_; j++) a += out_W[j] * lin2_b[j];
        g_effw[576] = a;
    }
}

// ---------------- persistent dataflow LSTM ----------------------------------
// item = 128(M) x 256(N); 8 warps (2m x 4n), warp tile 64x64 -> fragment
// re-reads cut 26%. Single-pass fp16; 4-stage bulk-DMA ring (prefetch 3).
__global__ __launch_bounds__(NTHR, 1)
void lstm_persist() {
    extern __shared__ __align__(128) char dynsm[];
    __shared__ __align__(8) unsigned long long s_full[NSTAGE], s_empty[NSTAGE];
    __shared__ int s_item;
    const uint32_t smb = smem_u32(dynsm);
    const uint32_t mb_full = smem_u32(s_full);
    const uint32_t mb_empty = smem_u32(s_empty);

    const int tid  = threadIdx.x;
    const int lane = tid & 31;
    const int wid  = tid >> 5;               // 0..7
    const int wm   = (wid & 1) * 64;         // 2 m-warps x 64
    const int wn   = (wid >> 1) * 64;        // 4 n-warps x 64

    const uint32_t a_off = (uint32_t)((wm + (lane & 15)) * ROWB + (lane >> 4) * 16);
    const uint32_t b_row = (uint32_t)(wn + (lane & 7) + ((lane >> 4) << 3));
    const uint32_t b_off = b_row * ROWB + (((lane >> 3) & 1) << 4);

    for (;;) {
        // ---- grab next item; init barriers ---------------------------------
        if (tid == 0) s_item = atomicAdd(&g_next, 1);
        __syncthreads();
        const int item = s_item;
        if (item >= NITEM) break;

        const int cell = item >> 6;
        const int tl = g_cell_tl[cell];
        const int t = tl >> 2, l = tl & 3;
        const int tile = item & 63;
        const int mBi = tile & 7, nBi = tile >> 3;
        const int nBase = nBi * 256;

        if (tid == 0) {
#pragma unroll
            for (int s = 0; s < NSTAGE; s++) {
                MBARRIER_INIT(mb_full + s * 8, 1);
                MBARRIER_INIT(mb_empty + s * 8, NTHR);
            }
        }
        __syncthreads();

        const uint8_t* wbase = g_Wt + (((size_t)l * 8 + nBi) * 16) * TBB;
        const uint8_t* a0base = (l == 0)
            ? g_xt + ((size_t)t * 64 + (size_t)mBi * 8) * TB
            : g_Ht + (((size_t)(t + 1) * L_ + (l - 1)) * 64 + (size_t)mBi * 8) * TB;
        const uint8_t* a1base = g_Ht + (((size_t)t * L_ + l) * 64 + (size_t)mBi * 8) * TB;

        auto issue_chunk = [&](int c) {      // tid==0 only
            const int s = c % NSTAGE;
            const uint32_t sb = smb + s * STAGE_BYTES;
            MBARRIER_EXPECT_TX(mb_full + s * 8, (uint32_t)STAGE_BYTES);
            cp_bulk(sb + B_OFF, wbase + (size_t)c * TBB, TBB, mb_full + s * 8);
            const uint8_t* asrc;
            if (c < 8) {
                if (c == 0 && l > 0) {
                    const int* p = &g_cnt[(t * L_ + (l - 1)) * 8 + mBi];
                    while (ld_acq(p) < 8) __nanosleep(32);
                }
                asrc = a0base + (size_t)c * TB;
            } else {
                if (c == 8 && t > 0) {
                    const int* p = &g_cnt[((t - 1) * L_ + l) * 8 + mBi];
                    while (ld_acq(p) < 8) __nanosleep(32);
                }
                asrc = a1base + (size_t)(c - 8) * TB;
            }
            cp_bulk(sb + A_OFF, asrc, TB, mb_full + s * 8);
        };

        float acc[4][8][4];
#pragma unroll
        for (int i = 0; i < 4; i++)
#pragma unroll
            for (int j = 0; j < 8; j++)
#pragma unroll
                for (int q = 0; q < 4; q++) acc[i][j][q] = 0.f;

        if (tid == 0)
            for (int c0 = 0; c0 < PREF; c0++) issue_chunk(c0);

        for (int c = 0; c < NCH; c++) {
            const int s = c % NSTAGE;
            const int k = c / NSTAGE;
            MBARRIER_WAIT_PARITY(mb_full + s * 8, k & 1);
            const uint32_t sb = smb + s * STAGE_BYTES;

#pragma unroll
            for (int kk = 0; kk < 4; kk++) {
                const uint32_t kofs = (uint32_t)(kk * 32);
                uint32_t afr[4][4];
#pragma unroll
                for (int mt = 0; mt < 4; mt++) {
                    uint32_t ad = sb + a_off + (uint32_t)(mt * 16 * ROWB) + kofs + A_OFF;
                    ldsm4(afr[mt], ad);
                }
                uint32_t bfr[8][2];
#pragma unroll
                for (int g = 0; g < 4; g++) {
                    uint32_t bd = sb + b_off + (uint32_t)(g * 16 * ROWB) + kofs + B_OFF;
                    uint32_t r[4];
                    ldsm4(r, bd);
                    bfr[2 * g][0] = r[0]; bfr[2 * g][1] = r[1];
                    bfr[2 * g + 1][0] = r[2]; bfr[2 * g + 1][1] = r[3];
                }
#pragma unroll
                for (int mt = 0; mt < 4; mt++)
#pragma unroll
                    for (int nt = 0; nt < 8; nt++) mma_f16(acc[mt][nt], afr[mt], bfr[nt]);
            }
            MBARRIER_ARRIVE(mb_empty + s * 8);

            const int cp = c + PREF;
            if (tid == 0 && cp < NCH) {
                const int sp = cp % NSTAGE;
                const int kp = cp / NSTAGE;
                if (kp >= 1) MBARRIER_WAIT_PARITY(mb_empty + sp * 8, (kp - 1) & 1);
                issue_chunk(cp);
            }
        }

        // ---- fused LSTM-cell epilogue (h written fp16, tiled) ----------------
        {
            const int q = lane & 3;
            const bool active = (q & 1) == 0;
            float* cbase = g_c + (size_t)l * B_ * HD_;
            uint8_t* hb = g_Ht + (((size_t)(t + 1) * L_ + l) * 64 + (size_t)mBi * 8) * TB;
            float* ys = (l == 2) ? (g_ys + (size_t)t * B_ * HD_) : nullptr;
            const int mBase = mBi * 128;

#pragma unroll
            for (int mt = 0; mt < 4; mt++) {
#pragma unroll
                for (int nt = 0; nt < 8; nt++) {
                    float* cc = acc[mt][nt];
                    float p0 = __shfl_xor_sync(0xffffffffu, cc[0], 1);
                    float p1 = __shfl_xor_sync(0xffffffffu, cc[1], 1);
                    float p2 = __shfl_xor_sync(0xffffffffu, cc[2], 1);
                    float p3 = __shfl_xor_sync(0xffffffffu, cc[3], 1);
                    if (active) {
                        int n0 = nBase + wn + nt * 8 + q * 2;
                        int j = n0 >> 2;
                        const float4 bs = *(const float4*)&g_bias[l * NG + n0];
                        int r0 = wm + mt * 16 + (lane >> 2);
                        uint8_t* hj = hb + (size_t)(j >> 6) * TB + (uint32_t)(j & 63) * 2;
#pragma unroll
                        for (int rg = 0; rg < 2; rg++) {
                            int rowin = r0 + rg * 8;
                            float gi = (rg ? cc[2] : cc[0]) + bs.x;
                            float gf = (rg ? cc[3] : cc[1]) + bs.y;
                            float gg = (rg ? p2 : p0) + bs.z;
                            float go = (rg ? p3 : p1) + bs.w;
                            size_t off = (size_t)(mBase + rowin) * HD_ + j;
                            float cold = cbase[off];
                            float cn = sigf(gf) * cold + sigf(gi) * tanhf(gg);
                            float hn = sigf(go) * tanhf(cn);
                            cbase[off] = cn;
                            *(__half*)(hj + (uint32_t)rowin * ROWB) = __float2half(hn);
                            if (ys) ys[off] = hn;
                        }
                    }
                }
            }
        }

        __threadfence();
        asm volatile("fence.proxy.async;" ::: "memory");
        __syncthreads();
        if (tid == 0) red_rel_add1(&g_cnt[(t * L_ + l) * 8 + mBi]);
    }
}

// ---------------- attention / TPA head --------------------------------------
// smem shrunk (conv_s + kW fp16) -> ~109KB -> 2 CTAs/SM.
#define HEAD_SMEM_BYTES (65536 + 32256 + 8064 + 2048 + 256 + 2048 + 256 + 1024 + 128)

__global__ __launch_bounds__(256)
void head_kernel(const float* __restrict__ conv_W, const float* __restrict__ conv_b,
                 const float* __restrict__ lin1_W, const float* __restrict__ lin1_b,
                 float* __restrict__ out) {
    extern __shared__ __align__(16) char smraw[];
    __half* conv_s  = (__half*)smraw;                       // [64][512] fp16
    float*  Hblk    = (float*)(smraw + 65536);              // [63][128]
    __half* kW_s    = (__half*)(smraw + 65536 + 32256);     // [64][63] fp16
    float*  htt_s   = (float*)(smraw + 65536 + 32256 + 8064);
    float*  w_s     = htt_s + 512;
    float*  alpha_s = w_s + 64;
    float*  v_s     = alpha_s + 512;
    float*  red_s   = v_s + 64;

    const int b = blockIdx.x;
    const int tid = threadIdx.x;
    const int lane = tid & 31;
    const int warp = tid >> 5;

    for (int i = tid; i < FN_ * ATT; i += 256) kW_s[i] = __float2half(conv_W[i]);
    for (int i = tid; i < HD_; i += 256)
        htt_s[i] = g_ys[(size_t)(T_ - 1) * B_ * HD_ + (size_t)b * HD_ + i];
    __syncthreads();

    for (int qq = 0; qq < 8; qq++) {
        int qi = warp * 8 + qq;
        float p = 0.f;
        for (int k = lane; k < HD_; k += 32) p += htt_s[k] * lin1_W[(size_t)qi * HD_ + k];
#pragma unroll
        for (int o = 16; o; o >>= 1) p += __shfl_xor_sync(0xffffffffu, p, o);
        if (lane == 0) w_s[qi] = p + lin1_b[qi];
    }

    float4* Hblk4 = (float4*)Hblk;
    const int fi4 = tid & 31;
    const int cgrp = tid >> 5;
    for (int fb = 0; fb < 4; fb++) {
        int f0 = fb * 128;
        for (int i = tid; i < ATT * 32; i += 256) {
            int tt = i >> 5, f4 = i & 31;
            float4 v = *(const float4*)&g_ys[(size_t)tt * B_ * HD_ + (size_t)b * HD_ + f0 + f4 * 4];
            v.x = fmaxf(v.x, 0.f); v.y = fmaxf(v.y, 0.f);
            v.z = fmaxf(v.z, 0.f); v.w = fmaxf(v.w, 0.f);
            Hblk4[i] = v;
        }
        __syncthreads();

        float4 acc[8];
#pragma unroll
        for (int k = 0; k < 8; k++) {
            float bb = conv_b[cgrp + 8 * k];
            acc[k] = make_float4(bb, bb, bb, bb);
        }
        for (int t = 0; t < ATT; t++) {
            float4 h = Hblk4[t * 32 + fi4];
#pragma unroll
            for (int k = 0; k < 8; k++) {
                float w = __half2float(kW_s[(cgrp + 8 * k) * ATT + t]);
                acc[k].x += w * h.x; acc[k].y += w * h.y;
                acc[k].z += w * h.z; acc[k].w += w * h.w;
            }
        }
#pragma unroll
        for (int k = 0; k < 8; k++) {
            int c = cgrp + 8 * k;
            float4 v = acc[k];
            __half2* dst = (__half2*)&conv_s[c * 512 + f0 + fi4 * 4];
            dst[0] = __floats2half2_rn(fmaxf(v.x, 0.f), fmaxf(v.y, 0.f));
            dst[1] = __floats2half2_rn(fmaxf(v.z, 0.f), fmaxf(v.w, 0.f));
        }
        __syncthreads();
    }

    for (int p = warp; p < 512; p += 8) {
        float a = __half2float(conv_s[p * 64 + lane]) * w_s[lane]
                + __half2float(conv_s[p * 64 + 32 + lane]) * w_s[32 + lane];
#pragma unroll
        for (int o = 16; o; o >>= 1) a += __shfl_xor_sync(0xffffffffu, a, o);
        if (lane == 0) alpha_s[p] = 1.f / (1.f + expf(-a));
    }
    __syncthreads();

    {
        int qn = tid & 63, part = tid >> 6;
        float a = 0.f;
        for (int p = part; p < 512; p += 4) a += alpha_s[p] * __half2float(conv_s[p * 64 + qn]);
        red_s[tid] = a;
    }
    __syncthreads();
    if (tid < 64) v_s[tid] = red_s[tid] + red_s[64 + tid] + red_s[128 + tid] + red_s[192 + tid];
    __syncthreads();

    float a = 0.f;
    for (int k = tid; k < HD_; k += 256) a += htt_s[k] * g_effw[k];
    if (tid < 64) a += v_s[tid] * g_effw[HD_ + tid];
#pragma unroll
    for (int o = 16; o; o >>= 1) a += __shfl_xor_sync(0xffffffffu, a, o);
    if (lane == 0) red_s[warp] = a;
    __syncthreads();
    if (tid == 0) {
        float tot = g_effw[576];
        for (int i = 0; i < 8; i++) tot += red_s[i];
        out[b] = tot;
    }
}

// ---------------- launch ----------------------------------------------------
extern "C" void kernel_launch(void* const* d_in, const int* in_sizes, int n_in,
                              void* d_out, int out_size) {
    const float* x      = (const float*)d_in[0];
    const float* W_ih   = (const float*)d_in[1];
    const float* W_hh   = (const float*)d_in[2];
    const float* b_ih   = (const float*)d_in[3];
    const float* b_hh   = (const float*)d_in[4];
    const float* conv_W = (const float*)d_in[5];
    const float* conv_b = (const float*)d_in[6];
    const float* lin1_W = (const float*)d_in[7];
    const float* lin1_b = (const float*)d_in[8];
    const float* lin2_W = (const float*)d_in[9];
    const float* lin2_b = (const float*)d_in[10];
    const float* out_W  = (const float*)d_in[11];
    const float* out_b  = (const float*)d_in[12];
    float* out = (float*)d_out;

    {   // prep (2 launches)
        size_t tw = (size_t)L_ * NG * KK;
        prep_w_kernel<<<(unsigned)((tw + 255) / 256), 256>>>(W_ih, W_hh, b_ih, b_hh);
        size_t tx = (size_t)T_ * B_ * D_;
        prep_misc_kernel<<<(unsigned)((tx + 255) / 256), 256>>>(x, lin2_W, lin2_b, out_W, out_b);
    }

    // persistent dataflow wavefront (single launch for all 192 cells)
    cudaFuncSetAttribute(lstm_persist, cudaFuncAttributeMaxDynamicSharedMemorySize, DYN_SMEM);
    lstm_persist<<<NPERS, NTHR, DYN_SMEM>>>();

    // head
    cudaFuncSetAttribute(head_kernel, cudaFuncAttributeMaxDynamicSharedMemorySize, HEAD_SMEM_BYTES);
    head_kernel<<<B_, 256, HEAD_SMEM_BYTES>>>(conv_W, conv_b, lin1_W, lin1_b, out);
}